// round 4
// baseline (speedup 1.0000x reference)
#include <cuda_runtime.h>

#define NN 16384
#define KN 25
#define DD 256
#define LL 64
#define NPB 8

// scratch for expected[N, D] (device-global: no allocation allowed)
__device__ float g_expected[NN * DD];

typedef unsigned long long ull;

__device__ __forceinline__ ull pk2(float lo, float hi) {
    ull r; asm("mov.b64 %0, {%1, %2};" : "=l"(r) : "f"(lo), "f"(hi)); return r;
}
__device__ __forceinline__ float2 upk2(ull v) {
    float2 f; asm("mov.b64 {%0, %1}, %2;" : "=f"(f.x), "=f"(f.y) : "l"(v)); return f;
}
// packed fp32x2 FMA (Blackwell): 2 MACs per instruction, ptxas never emits from C++
__device__ __forceinline__ ull ffma2(ull a, ull b, ull c) {
    ull d; asm("fma.rn.f32x2 %0, %1, %2, %3;" : "=l"(d) : "l"(a), "l"(b), "l"(c)); return d;
}

// ---------------------------------------------------------------------------
// Kernel A: fused gate + link-conditioned amplification + mean over K
//   expected[n,d] = (1/K) * sum_k neigh[n,k,d] * sigmoid((link[n,k]@W_link)[d])
//                          * sigmoid(ts[n] + tn[n,k] + tl[n,k]) / p[n,k]
// One 256-thread block handles NPB nodes; thread t owns output dim d=t.
// W_link column t lives in registers as 32 f32x2 pairs (amortized over NPB nodes).
// ---------------------------------------------------------------------------
__global__ __launch_bounds__(256) void gate_agg_kernel(
    const float* __restrict__ self_vecs,
    const float* __restrict__ neigh_vecs,
    const float* __restrict__ link_vecs,
    const float* __restrict__ select_probs,
    const float* __restrict__ g_self_w,
    const float* __restrict__ g_neigh_w,
    const float* __restrict__ g_link_w,
    const float* __restrict__ W_link)
{
    __shared__ alignas(16) float link_s[KN * LL];   // 6.4 KB, one node's link rows
    __shared__ float part_s[KN + 1][DD];            // 26.6 KB, batched reduction staging
    __shared__ float red_s[KN + 1];
    __shared__ float wk_s[KN];
    __shared__ float glw_s[LL];

    const int t    = threadIdx.x;
    const int warp = t >> 5;
    const int lane = t & 31;

    const float gnw = g_neigh_w[t];
    const float gsw = g_self_w[t];
    if (t < LL) glw_s[t] = g_link_w[t];

    // W_link[:, t] packed along L in pairs -> 32 x f32x2 in registers
    ull wl2[LL / 2];
#pragma unroll
    for (int p = 0; p < LL / 2; p++) {
        wl2[p] = pk2(W_link[(2 * p) * DD + t], W_link[(2 * p + 1) * DD + t]);
    }

    for (int i = 0; i < NPB; i++) {
        const int n = blockIdx.x * NPB + i;

        __syncthreads();  // protect link_s reuse across nodes
        // load this node's link rows (25*64 f32 = 400 float4, coalesced)
#pragma unroll
        for (int u = 0; u < 2; u++) {
            int idx = t + u * 256;
            if (idx < (KN * LL) / 4)
                ((float4*)link_s)[idx] =
                    ((const float4*)(link_vecs + (size_t)n * KN * LL))[idx];
        }
        float x = self_vecs[n * DD + t];
        __syncthreads();

        // pass 1: load neigh ONCE into registers; stage gate-dot partials
        float v[KN];
#pragma unroll
        for (int k = 0; k < KN; k++) {
            v[k] = neigh_vecs[((size_t)n * KN + k) * DD + t];
            float pp = v[k] * gnw;
            if (t < LL) pp = fmaf(link_s[k * LL + t], glw_s[t], pp);
            part_s[k][t] = pp;
        }
        part_s[KN][t] = x * gsw;  // trans_self partial as the 26th reduction task
        __syncthreads();

        // batched block reduction: 26 sums of 256 values, one warp per task
        for (int task = warp; task < KN + 1; task += 8) {
            float s = 0.f;
#pragma unroll
            for (int q = 0; q < 8; q++) s += part_s[task][lane + 32 * q];
#pragma unroll
            for (int o = 16; o > 0; o >>= 1) s += __shfl_xor_sync(0xffffffffu, s, o);
            if (lane == 0) red_s[task] = s;
        }
        __syncthreads();
        if (t < KN) {
            float r    = red_s[t] + red_s[KN];
            float gate = 1.f / (1.f + __expf(-r));
            wk_s[t]    = gate / (select_probs[n * KN + t] * (float)KN);
        }
        __syncthreads();

        // pass 2: trans_links dot (FFMA2, L packed in pairs) + sigmoid + weighted mean
        float acc = 0.f;
#pragma unroll
        for (int k = 0; k < KN; k++) {
            ull a2 = 0ull;
            const float4* lk4 = (const float4*)(link_s + k * LL);
#pragma unroll
            for (int p = 0; p < LL / 4; p++) {
                float4 q4 = lk4[p];                         // LDS.128 broadcast
                a2 = ffma2(pk2(q4.x, q4.y), wl2[2 * p],     a2);
                a2 = ffma2(pk2(q4.z, q4.w), wl2[2 * p + 1], a2);
            }
            float2 af = upk2(a2);
            float tl  = af.x + af.y;
            float sg  = 1.f / (1.f + __expf(-tl));
            acc = fmaf(v[k] * sg, wk_s[k], acc);
        }
        g_expected[(size_t)n * DD + t] = acc;
    }
}

// ---------------------------------------------------------------------------
// Kernel B: out[:, coff:coff+256] = relu(A @ W),  A:[N,256], W:[256,256]
// 64x64 tile per 256-thread block, 4x4 outputs/thread, FFMA2-packed columns.
// use_expected selects the device-global expected buffer as A.
// ---------------------------------------------------------------------------
__global__ __launch_bounds__(256) void gemm_relu_kernel(
    const float* __restrict__ A_in,
    const float* __restrict__ W,
    float* __restrict__ out,
    int coff, int use_expected)
{
    const float* __restrict__ A = use_expected ? (const float*)g_expected : A_in;

    __shared__ float As[64][32];
    __shared__ float Ws[32][64];

    const int tid = threadIdx.x;
    const int tx  = tid & 15;   // 16 col-groups of 4
    const int ty  = tid >> 4;   // 16 row-groups of 4
    const int r0  = blockIdx.x * 64;
    const int c0  = blockIdx.y * 64;

    ull acc[4][2];
#pragma unroll
    for (int i = 0; i < 4; i++) { acc[i][0] = 0ull; acc[i][1] = 0ull; }

    for (int kb = 0; kb < DD; kb += 32) {
#pragma unroll
        for (int u = 0; u < 2; u++) {            // A tile: 64x32, float4 coalesced
            int idx = tid + u * 256;
            int m = idx >> 3, q = idx & 7;
            *(float4*)&As[m][q * 4] =
                *(const float4*)&A[(size_t)(r0 + m) * DD + kb + q * 4];
        }
#pragma unroll
        for (int u = 0; u < 2; u++) {            // W tile: 32x64, float4 coalesced
            int idx = tid + u * 256;
            int kk = idx >> 4, q = idx & 15;
            *(float4*)&Ws[kk][q * 4] =
                *(const float4*)&W[(size_t)(kb + kk) * DD + c0 + q * 4];
        }
        __syncthreads();
#pragma unroll
        for (int kk = 0; kk < 32; kk++) {
            float4 b4 = *(const float4*)&Ws[kk][tx * 4];
            ull b01 = pk2(b4.x, b4.y);
            ull b23 = pk2(b4.z, b4.w);
#pragma unroll
            for (int i = 0; i < 4; i++) {
                float a = As[ty * 4 + i][kk];    // 2-address broadcast, conflict-free
                ull aa = pk2(a, a);
                acc[i][0] = ffma2(aa, b01, acc[i][0]);
                acc[i][1] = ffma2(aa, b23, acc[i][1]);
            }
        }
        __syncthreads();
    }

#pragma unroll
    for (int i = 0; i < 4; i++) {
        float2 r01 = upk2(acc[i][0]);
        float2 r23 = upk2(acc[i][1]);
        float4 o;
        o.x = fmaxf(r01.x, 0.f);
        o.y = fmaxf(r01.y, 0.f);
        o.z = fmaxf(r23.x, 0.f);
        o.w = fmaxf(r23.y, 0.f);
        *(float4*)&out[(size_t)(r0 + ty * 4 + i) * 512 + coff + c0 + tx * 4] = o;
    }
}

extern "C" void kernel_launch(void* const* d_in, const int* in_sizes, int n_in,
                              void* d_out, int out_size)
{
    const float* self_vecs    = (const float*)d_in[0];
    const float* neigh_vecs   = (const float*)d_in[1];
    const float* link_vecs    = (const float*)d_in[2];
    const float* select_probs = (const float*)d_in[3];
    const float* g_self_w     = (const float*)d_in[4];
    const float* g_neigh_w    = (const float*)d_in[5];
    const float* g_link_w     = (const float*)d_in[6];
    const float* W_link       = (const float*)d_in[7];
    const float* W_self       = (const float*)d_in[8];
    const float* W_neigh      = (const float*)d_in[9];
    float* out = (float*)d_out;

    gate_agg_kernel<<<NN / NPB, 256>>>(self_vecs, neigh_vecs, link_vecs, select_probs,
                                       g_self_w, g_neigh_w, g_link_w, W_link);

    dim3 g(NN / 64, 256 / 64);
    gemm_relu_kernel<<<g, 256>>>(self_vecs, W_self, out, 0, 0);
    gemm_relu_kernel<<<g, 256>>>(nullptr, W_neigh, out, 256, 1);
}